// round 16
// baseline (speedup 1.0000x reference)
#include <cuda_runtime.h>
#include <cuda_bf16.h>
#include <math.h>
#include <math_constants.h>
#include <cstdint>

#define T_   2048
#define DM_  4096
#define H_   16
#define HD_  256
#define RD_  64
#define DFF_ 16384

// ---------------- scratch (device globals) ----------------
__device__ __nv_bfloat16 g_wqkvT_hi[(size_t)3*DM_*DM_];
__device__ __nv_bfloat16 g_wqkvT_lo[(size_t)3*DM_*DM_];
__device__ __nv_bfloat16 g_woutT_hi[(size_t)DM_*DM_];
__device__ __nv_bfloat16 g_woutT_lo[(size_t)DM_*DM_];
__device__ __nv_bfloat16 g_wfciT_hi[(size_t)DFF_*DM_];
__device__ __nv_bfloat16 g_wfciT_lo[(size_t)DFF_*DM_];
__device__ __nv_bfloat16 g_wfcoT_hi[(size_t)DM_*DFF_];
__device__ __nv_bfloat16 g_wfcoT_lo[(size_t)DM_*DFF_];
__device__ __nv_bfloat16 g_ln_hi[(size_t)T_*DM_];
__device__ __nv_bfloat16 g_ln_lo[(size_t)T_*DM_];
__device__ __nv_bfloat16 g_act_hi[(size_t)T_*DFF_];
__device__ __nv_bfloat16 g_act_lo[(size_t)T_*DFF_];
__device__ __nv_bfloat16 g_ctx_hi[(size_t)T_*DM_];
__device__ __nv_bfloat16 g_ctx_lo[(size_t)T_*DM_];
__device__ float g_qkv[(size_t)T_*3*DM_];
__device__ float g_attnout[(size_t)T_*DM_];
// attention operand buffers ([H][T][HD] for q,k; [H][HD][T] for v transposed)
__device__ __nv_bfloat16 g_qh[(size_t)T_*DM_];
__device__ __nv_bfloat16 g_ql[(size_t)T_*DM_];
__device__ __nv_bfloat16 g_kh[(size_t)T_*DM_];
__device__ __nv_bfloat16 g_kl[(size_t)T_*DM_];
__device__ __nv_bfloat16 g_vth[(size_t)T_*DM_];
__device__ __nv_bfloat16 g_vtl[(size_t)T_*DM_];

// ---------------- PTX helpers (baseline features only) --------
__device__ __forceinline__ uint32_t smem_u32(const void* p) {
    uint32_t a;
    asm("{ .reg .u64 t; cvta.to.shared.u64 t, %1; cvt.u32.u64 %0, t; }" : "=r"(a) : "l"(p));
    return a;
}
__device__ __forceinline__ void cp_async16(uint32_t d, const void* g) {
    asm volatile("cp.async.cg.shared.global [%0], [%1], 16;" :: "r"(d), "l"(g));
}
#define CP_COMMIT()  asm volatile("cp.async.commit_group;" ::: "memory")
#define CP_WAIT1()   asm volatile("cp.async.wait_group 1;" ::: "memory")
#define CP_WAIT0()   asm volatile("cp.async.wait_group 0;" ::: "memory")

__device__ __forceinline__ void ldsm4(uint32_t* r, uint32_t addr) {
    asm volatile("ldmatrix.sync.aligned.m8n8.x4.shared.b16 {%0,%1,%2,%3}, [%4];"
                 : "=r"(r[0]), "=r"(r[1]), "=r"(r[2]), "=r"(r[3]) : "r"(addr));
}
__device__ __forceinline__ void mma16816(float* c, const uint32_t* a,
                                         uint32_t b0, uint32_t b1) {
    asm volatile("mma.sync.aligned.m16n8k16.row.col.f32.bf16.bf16.f32 "
                 "{%0,%1,%2,%3}, {%4,%5,%6,%7}, {%8,%9}, {%0,%1,%2,%3};"
                 : "+f"(c[0]), "+f"(c[1]), "+f"(c[2]), "+f"(c[3])
                 : "r"(a[0]), "r"(a[1]), "r"(a[2]), "r"(a[3]), "r"(b0), "r"(b1));
}
__device__ __forceinline__ uint32_t pack_bf16x2(float lo, float hi) {
    uint32_t r;
    asm("cvt.rn.bf16x2.f32 %0, %1, %2;" : "=r"(r) : "f"(hi), "f"(lo));
    return r;
}
__device__ __forceinline__ void split_store(float v, __nv_bfloat16* ph, __nv_bfloat16* pl) {
    __nv_bfloat16 h = __float2bfloat16(v);
    *ph = h;
    *pl = __float2bfloat16(v - __bfloat162float(h));
}

// ---------------- weight transpose + bf16 split (coalesced bf16x2 stores) ---
__global__ void convT_kernel(const float* __restrict__ W,
                             __nv_bfloat16* __restrict__ hi,
                             __nv_bfloat16* __restrict__ lo,
                             int Krows, int Ncols) {
    __shared__ float tile[32][33];
    int n0 = blockIdx.x * 32, k0 = blockIdx.y * 32;
    int tx = threadIdx.x, ty = threadIdx.y;       // 32 x 8
#pragma unroll
    for (int i = 0; i < 4; i++)
        tile[ty + 8 * i][tx] = W[(size_t)(k0 + ty + 8 * i) * Ncols + n0 + tx];
    __syncthreads();
#pragma unroll
    for (int it = 0; it < 2; it++) {
        int r  = ty + 8 * (2 * it + (tx >> 4));   // n within tile
        int kp = (tx & 15) * 2;                   // k pair
        float v0 = tile[kp][r], v1 = tile[kp + 1][r];
        size_t o = (size_t)(n0 + r) * Krows + k0 + kp;
        __nv_bfloat16 h0 = __float2bfloat16(v0);
        __nv_bfloat16 h1 = __float2bfloat16(v1);
        __nv_bfloat162 hh; hh.x = h0; hh.y = h1;
        *(__nv_bfloat162*)(hi + o) = hh;
        __nv_bfloat162 ll;
        ll.x = __float2bfloat16(v0 - __bfloat162float(h0));
        ll.y = __float2bfloat16(v1 - __bfloat162float(h1));
        *(__nv_bfloat162*)(lo + o) = ll;
    }
}

// ---------------- LayerNorm -> bf16 hi/lo ----------------
__global__ void ln_kernel(const float* __restrict__ x,
                          const float* __restrict__ gamma,
                          const float* __restrict__ beta,
                          __nv_bfloat16* __restrict__ ohi,
                          __nv_bfloat16* __restrict__ olo) {
    int row = blockIdx.x;
    const float4* xr = (const float4*)(x + (size_t)row * DM_);
    float4 v[4];
    float sum = 0.f, sq = 0.f;
#pragma unroll
    for (int i = 0; i < 4; i++) {
        v[i] = xr[threadIdx.x + 256 * i];
        sum += v[i].x + v[i].y + v[i].z + v[i].w;
        sq  += v[i].x * v[i].x + v[i].y * v[i].y + v[i].z * v[i].z + v[i].w * v[i].w;
    }
#pragma unroll
    for (int o = 16; o; o >>= 1) {
        sum += __shfl_xor_sync(0xffffffffu, sum, o);
        sq  += __shfl_xor_sync(0xffffffffu, sq,  o);
    }
    __shared__ float ssum[8], ssq[8];
    int warp = threadIdx.x >> 5, lane = threadIdx.x & 31;
    if (lane == 0) { ssum[warp] = sum; ssq[warp] = sq; }
    __syncthreads();
    sum = 0.f; sq = 0.f;
#pragma unroll
    for (int i = 0; i < 8; i++) { sum += ssum[i]; sq += ssq[i]; }
    float mu  = sum * (1.0f / DM_);
    float var = sq * (1.0f / DM_) - mu * mu;
    float inv = rsqrtf(var + 1e-5f);
    const float4* g4 = (const float4*)gamma;
    const float4* b4 = (const float4*)beta;
#pragma unroll
    for (int i = 0; i < 4; i++) {
        int idx = threadIdx.x + 256 * i;
        float4 g = g4[idx], b = b4[idx];
        size_t base = (size_t)row * DM_ + idx * 4;
        split_store((v[i].x - mu) * inv * g.x + b.x, ohi + base + 0, olo + base + 0);
        split_store((v[i].y - mu) * inv * g.y + b.y, ohi + base + 1, olo + base + 1);
        split_store((v[i].z - mu) * inv * g.z + b.z, ohi + base + 2, olo + base + 2);
        split_store((v[i].w - mu) * inv * g.w + b.w, ohi + base + 3, olo + base + 3);
    }
}

// ---------------- fused RoPE + q/k split to [H][T][HD] bf16 hi/lo -----------
__global__ void qksplit_rope(const float* __restrict__ qkv,
                             const int* __restrict__ positions,
                             __nv_bfloat16* __restrict__ qh, __nv_bfloat16* __restrict__ ql,
                             __nv_bfloat16* __restrict__ kh, __nv_bfloat16* __restrict__ kl) {
    int idx = blockIdx.x * 256 + threadIdx.x;          // 0 .. 2*T*DM/4
    const int per = T_ * DM_ / 4;
    int half = idx >= per;
    int rem = idx - half * per;
    int t = rem / (DM_ / 4);
    int e4 = rem - t * (DM_ / 4);
    float4 v = *(const float4*)(qkv + (size_t)t * (3 * DM_) + half * DM_ + e4 * 4);
    int hh = (e4 * 4) >> 8;
    int hd = (e4 * 4) & 255;
    if (hd < RD_) {
        // GPT-J rope: pairs (hd,hd+1)=(v.x,v.y) at i=hd/2 and (hd+2,hd+3)=(v.z,v.w) at i=hd/2+1
        int i0 = hd >> 1;
        float p = (float)positions[t];
        float inv0 = (float)pow(10000.0, -(double)i0 / 32.0);
        float inv1 = (float)pow(10000.0, -(double)(i0 + 1) / 32.0);
        float s0, c0, s1, c1;
        sincosf(p * inv0, &s0, &c0);
        sincosf(p * inv1, &s1, &c1);
        float x1 = v.x, x2 = v.y;
        v.x = x1 * c0 - x2 * s0;
        v.y = x2 * c0 + x1 * s0;
        x1 = v.z; x2 = v.w;
        v.z = x1 * c1 - x2 * s1;
        v.w = x2 * c1 + x1 * s1;
    }
    size_t dst = ((size_t)(hh * T_ + t)) * 256 + hd;
    __nv_bfloat16 *oh = half ? kh : qh, *ol = half ? kl : ql;
    split_store(v.x, oh + dst + 0, ol + dst + 0);
    split_store(v.y, oh + dst + 1, ol + dst + 1);
    split_store(v.z, oh + dst + 2, ol + dst + 2);
    split_store(v.w, oh + dst + 3, ol + dst + 3);
}

// ---------------- v split + transpose to [H][HD][T] bf16 hi/lo --------
__global__ void vsplitT_kernel(const float* __restrict__ qkv,
                               __nv_bfloat16* __restrict__ vth, __nv_bfloat16* __restrict__ vtl) {
    __shared__ float tile[32][33];
    int t0 = blockIdx.x * 32, hd0 = blockIdx.y * 32, h = blockIdx.z;
    int tx = threadIdx.x, ty = threadIdx.y;
#pragma unroll
    for (int i = 0; i < 4; i++)
        tile[ty + 8 * i][tx] = qkv[(size_t)(t0 + ty + 8 * i) * (3 * DM_) + 2 * DM_ + h * 256 + hd0 + tx];
    __syncthreads();
#pragma unroll
    for (int i = 0; i < 4; i++) {
        int r = ty + 8 * i;                 // hd within tile
        float v = tile[tx][r];              // = V[t0+tx][hd0+r]
        size_t o = ((size_t)(h * 256 + hd0 + r)) * T_ + t0 + tx;
        split_store(v, vth + o, vtl + o);
    }
}

__device__ __forceinline__ float gelu_tanh(float x) {
    float x3 = x * x * x;
    float t  = tanhf(0.7978845608028654f * (x + 0.044715f * x3));
    return 0.5f * x * (1.0f + t);
}

// ---------------- final merge: out += attnout ----------------
__global__ void add_kernel(float* __restrict__ out, const float* __restrict__ a) {
    int i = blockIdx.x * blockDim.x + threadIdx.x;
    float4 o = ((const float4*)out)[i];
    float4 v = ((const float4*)a)[i];
    o.x += v.x; o.y += v.y; o.z += v.z; o.w += v.w;
    ((float4*)out)[i] = o;
}

// ---------------- mma.sync split-bf16 GEMM (unchanged from R10) -------
#define KC 32
#define ARR_BYTES 8192
#define AHI_OFF 0
#define ALO_OFF 8192
#define BHI_OFF 16384
#define BLO_OFF 24576
#define STAGE_BYTES 32768
#define NSTAGE 3
#define GEMM_SMEM (NSTAGE * STAGE_BYTES)

template <int EPI>
__global__ void __launch_bounds__(256, 2)
mma_gemm(const __nv_bfloat16* __restrict__ Ahi, const __nv_bfloat16* __restrict__ Alo,
         const __nv_bfloat16* __restrict__ Bhi, const __nv_bfloat16* __restrict__ Blo,
         float* __restrict__ C,
         __nv_bfloat16* __restrict__ Ohi, __nv_bfloat16* __restrict__ Olo,
         const float* __restrict__ bias, const float* __restrict__ res,
         int M, int N, int K) {
    extern __shared__ char smem[];
    const uint32_t sb0 = smem_u32(smem);
    int tid = threadIdx.x;
    int lane = tid & 31, wid = tid >> 5;
    int wm = wid >> 2, wn = wid & 3;

    int nbn = N / 128, nbm = M / 128;
    const int SWT = 8;
    int per = SWT * nbm;
    int ggrp = blockIdx.x / per, rem = blockIdx.x - ggrp * per;
    int bn0 = ggrp * SWT;
    int w = nbn - bn0; if (w > SWT) w = SWT;
    int bn = bn0 + rem % w;
    int bm = rem / w;

    float acc[4][4][4];
#pragma unroll
    for (int i = 0; i < 4; i++)
#pragma unroll
        for (int j = 0; j < 4; j++)
#pragma unroll
            for (int q = 0; q < 4; q++) acc[i][j][q] = 0.f;

    auto load_stage = [&](int s, int k0) {
        uint32_t sb = sb0 + s * STAGE_BYTES;
#pragma unroll
        for (int j = 0; j < 2; j++) {
            int id  = tid + 256 * j;
            int row = id >> 2, c = id & 3;
            uint32_t d = row * 64 + ((c ^ ((row >> 1) & 3)) << 4);
            size_t goA = (size_t)(bm * 128 + row) * K + k0 + c * 8;
            size_t goB = (size_t)(bn * 128 + row) * K + k0 + c * 8;
            cp_async16(sb + AHI_OFF + d, Ahi + goA);
            cp_async16(sb + ALO_OFF + d, Alo + goA);
            cp_async16(sb + BHI_OFF + d, Bhi + goB);
            cp_async16(sb + BLO_OFF + d, Blo + goB);
        }
    };

    load_stage(0, 0); CP_COMMIT();
    load_stage(1, KC); CP_COMMIT();

    int hi4 = lane >> 4;
    int rA[4], swA[4], rB0, rB1, swB0, swB1;
#pragma unroll
    for (int i = 0; i < 4; i++) {
        int r = wm * 64 + i * 16 + (lane & 15);
        rA[i] = r * 64;
        swA[i] = (r >> 1) & 3;
    }
    {
        int r0 = wn * 32 + (lane & 15);
        int r1 = r0 + 16;
        rB0 = r0 * 64; swB0 = (r0 >> 1) & 3;
        rB1 = r1 * 64; swB1 = (r1 >> 1) & 3;
    }

    int nk = K / KC;
    int st = 0, ld = 2;
    for (int kc = 0; kc < nk; kc++) {
        CP_WAIT1();
        __syncthreads();
        if (kc + 2 < nk) load_stage(ld, (kc + 2) * KC);
        CP_COMMIT();
        uint32_t base = sb0 + st * STAGE_BYTES;
#pragma unroll
        for (int ks = 0; ks < 2; ks++) {
            int c = ks * 2 + hi4;
            uint32_t bh[8], bl[8];
            ldsm4(bh,     base + BHI_OFF + rB0 + ((c ^ swB0) << 4));
            ldsm4(bh + 4, base + BHI_OFF + rB1 + ((c ^ swB1) << 4));
            ldsm4(bl,     base + BLO_OFF + rB0 + ((c ^ swB0) << 4));
            ldsm4(bl + 4, base + BLO_OFF + rB1 + ((c ^ swB1) << 4));
#pragma unroll
            for (int i = 0; i < 4; i++) {
                uint32_t ah[4], al[4];
                ldsm4(ah, base + AHI_OFF + rA[i] + ((c ^ swA[i]) << 4));
                ldsm4(al, base + ALO_OFF + rA[i] + ((c ^ swA[i]) << 4));
#pragma unroll
                for (int j = 0; j < 4; j++) {
                    int j2 = j >> 1, ss = j & 1;
                    uint32_t b0h = bh[j2 * 4 + ss], b1h = bh[j2 * 4 + ss + 2];
                    uint32_t b0l = bl[j2 * 4 + ss], b1l = bl[j2 * 4 + ss + 2];
                    mma16816(acc[i][j], ah, b0h, b1h);
                    mma16816(acc[i][j], ah, b0l, b1l);
                    mma16816(acc[i][j], al, b0h, b1h);
                }
            }
        }
        st = (st == 2) ? 0 : st + 1;
        ld = (ld == 2) ? 0 : ld + 1;
    }

    int gq = lane >> 2, cc = lane & 3;
#pragma unroll
    for (int i = 0; i < 4; i++) {
#pragma unroll
        for (int j = 0; j < 4; j++) {
            int row = bm * 128 + wm * 64 + i * 16 + gq;
            int col = bn * 128 + wn * 32 + j * 8 + 2 * cc;
            float* a4 = acc[i][j];
#pragma unroll
            for (int half = 0; half < 2; half++) {
                int r = row + 8 * half;
                float v0 = a4[2 * half], v1 = a4[2 * half + 1];
                size_t base = (size_t)r * N + col;
                if (EPI == 0) {
                    *(float2*)(C + base) = make_float2(v0, v1);
                } else if (EPI == 1) {
                    float g0 = gelu_tanh(v0 + bias[col]);
                    float g1 = gelu_tanh(v1 + bias[col + 1]);
                    split_store(g0, Ohi + base, Olo + base);
                    split_store(g1, Ohi + base + 1, Olo + base + 1);
                } else if (EPI == 2) {
                    float2 rr = *(const float2*)(res + base);
                    *(float2*)(C + base) = make_float2(v0 + bias[col] + rr.x,
                                                       v1 + bias[col + 1] + rr.y);
                } else {
                    float2 cur = *(float2*)(C + base);
                    *(float2*)(C + base) = make_float2(cur.x + v0, cur.y + v1);
                }
            }
        }
    }
}

// ---------------- tensor-core causal flash attention ----------------
// 128KB smem (single-buffered KV) so a 96KB GEMM CTA co-resides on the SM.
// CTA: 64 q rows x one head, 128 threads (4 warps x 16 rows).
#define BQ2 64
#define BK2 32
#define SMQ_HI 0
#define SMQ_LO 32768
#define SMK_HI 65536
#define SMK_LO 81920
#define SMV_HI 98304
#define SMV_LO 114688
#define ATT_SMEM 131072

__global__ void __launch_bounds__(128, 1)
attn_mma(const __nv_bfloat16* __restrict__ qh, const __nv_bfloat16* __restrict__ ql,
         const __nv_bfloat16* __restrict__ kh, const __nv_bfloat16* __restrict__ kl,
         const __nv_bfloat16* __restrict__ vth, const __nv_bfloat16* __restrict__ vtl,
         __nv_bfloat16* __restrict__ chi, __nv_bfloat16* __restrict__ clo) {
    extern __shared__ char smem[];
    uint32_t sb = smem_u32(smem);
    int h = blockIdx.y;
    int qb = (gridDim.x - 1) - blockIdx.x;      // big tiles first
    int tid = threadIdx.x, lane = tid & 31, w = tid >> 5;

    auto load_q = [&]() {
#pragma unroll
        for (int j = 0; j < 16; j++) {
            int id = tid + 128 * j;             // 0..2047
            int row = id >> 5, c = id & 31;
            uint32_t d = row * 512 + ((c ^ ((row & 7) << 2)) << 4);
            size_t src = ((size_t)(h * T_ + qb * BQ2 + row)) * 256 + c * 8;
            cp_async16(sb + SMQ_HI + d, qh + src);
            cp_async16(sb + SMQ_LO + d, ql + src);
        }
    };
    auto load_kv = [&](int kt) {
#pragma unroll
        for (int j = 0; j < 8; j++) {
            int id = tid + 128 * j;             // 0..1023
            int row = id >> 5, c = id & 31;
            uint32_t d = row * 512 + ((c ^ ((row & 7) << 2)) << 4);
            size_t src = ((size_t)(h * T_ + kt * BK2 + row)) * 256 + c * 8;
            cp_async16(sb + SMK_HI + d, kh + src);
            cp_async16(sb + SMK_LO + d, kl + src);
            int vrow = id >> 2, vc = id & 3;
            uint32_t vd = vrow * 64 + ((vc ^ ((vrow >> 1) & 3)) << 4);
            size_t vs = ((size_t)(h * 256 + vrow)) * T_ + kt * BK2 + vc * 8;
            cp_async16(sb + SMV_HI + vd, vth + vs);
            cp_async16(sb + SMV_LO + vd, vtl + vs);
        }
    };

    float ctx[32][4];
#pragma unroll
    for (int i = 0; i < 32; i++)
#pragma unroll
        for (int q = 0; q < 4; q++) ctx[i][q] = 0.f;
    float m0 = -CUDART_INF_F, m1 = -CUDART_INF_F, l0 = 0.f, l1 = 0.f;

    int ntiles = 2 * qb + 2;
    load_q(); CP_COMMIT();
    for (int kt = 0; kt < ntiles; kt++) {
        load_kv(kt); CP_COMMIT();
        CP_WAIT0();
        __syncthreads();

        // ---- S = Q K^T (3-pass split) ----
        float sacc[4][4];
#pragma unroll
        for (int nb = 0; nb < 4; nb++)
#pragma unroll
            for (int q = 0; q < 4; q++) sacc[nb][q] = 0.f;
#pragma unroll 4
        for (int ks = 0; ks < 16; ks++) {
            int arow = w * 16 + (lane & 15);
            int ac = ks * 2 + (lane >> 4);
            uint32_t aoff = arow * 512 + ((ac ^ ((arow & 7) << 2)) << 4);
            uint32_t qhf[4], qlf[4];
            ldsm4(qhf, sb + SMQ_HI + aoff);
            ldsm4(qlf, sb + SMQ_LO + aoff);
            uint32_t kbh[8], kbl[8];
#pragma unroll
            for (int p2 = 0; p2 < 2; p2++) {
                int krow = p2 * 16 + (lane & 15);
                uint32_t koff = krow * 512 + ((ac ^ ((krow & 7) << 2)) << 4);
                ldsm4(kbh + 4 * p2, sb + SMK_HI + koff);
                ldsm4(kbl + 4 * p2, sb + SMK_LO + koff);
            }
#pragma unroll
            for (int nb = 0; nb < 4; nb++) {
                int p2 = nb >> 1, ss = nb & 1;
                mma16816(sacc[nb], qhf, kbh[p2 * 4 + ss], kbh[p2 * 4 + ss + 2]);
            }
#pragma unroll
            for (int nb = 0; nb < 4; nb++) {
                int p2 = nb >> 1, ss = nb & 1;
                mma16816(sacc[nb], qhf, kbl[p2 * 4 + ss], kbl[p2 * 4 + ss + 2]);
            }
#pragma unroll
            for (int nb = 0; nb < 4; nb++) {
                int p2 = nb >> 1, ss = nb & 1;
                mma16816(sacc[nb], qlf, kbh[p2 * 4 + ss], kbh[p2 * 4 + ss + 2]);
            }
        }

        // ---- mask + online softmax ----
        int r0 = qb * BQ2 + w * 16 + (lane >> 2);
        int r1 = r0 + 8;
        float mloc0 = -CUDART_INF_F, mloc1 = -CUDART_INF_F;
#pragma unroll
        for (int nb = 0; nb < 4; nb++) {
            int colb = kt * BK2 + nb * 8 + (lane & 3) * 2;
#pragma unroll
            for (int e = 0; e < 2; e++) {
                float v0 = sacc[nb][e] * 0.0625f;
                float v1 = sacc[nb][2 + e] * 0.0625f;
                if (colb + e > r0) v0 = -CUDART_INF_F;
                if (colb + e > r1) v1 = -CUDART_INF_F;
                sacc[nb][e] = v0; sacc[nb][2 + e] = v1;
                mloc0 = fmaxf(mloc0, v0); mloc1 = fmaxf(mloc1, v1);
            }
        }
        mloc0 = fmaxf(mloc0, __shfl_xor_sync(0xffffffffu, mloc0, 1));
        mloc0 = fmaxf(mloc0, __shfl_xor_sync(0xffffffffu, mloc0, 2));
        mloc1 = fmaxf(mloc1, __shfl_xor_sync(0xffffffffu, mloc1, 1));
        mloc1 = fmaxf(mloc1, __shfl_xor_sync(0xffffffffu, mloc1, 2));
        float mn0 = fmaxf(m0, mloc0), mn1 = fmaxf(m1, mloc1);
        float al0 = __expf(m0 - mn0), al1 = __expf(m1 - mn1);
        float ls0 = 0.f, ls1 = 0.f;
#pragma unroll
        for (int nb = 0; nb < 4; nb++) {
#pragma unroll
            for (int e = 0; e < 2; e++) {
                float p0 = __expf(sacc[nb][e] - mn0);
                float p1 = __expf(sacc[nb][2 + e] - mn1);
                ls0 += p0; ls1 += p1;
                sacc[nb][e] = p0; sacc[nb][2 + e] = p1;
            }
        }
        ls0 += __shfl_xor_sync(0xffffffffu, ls0, 1);
        ls0 += __shfl_xor_sync(0xffffffffu, ls0, 2);
        ls1 += __shfl_xor_sync(0xffffffffu, ls1, 1);
        ls1 += __shfl_xor_sync(0xffffffffu, ls1, 2);
        l0 = l0 * al0 + ls0;
        l1 = l1 * al1 + ls1;
        m0 = mn0; m1 = mn1;
#pragma unroll
        for (int nv = 0; nv < 32; nv++) {
            ctx[nv][0] *= al0; ctx[nv][1] *= al0;
            ctx[nv][2] *= al1; ctx[nv][3] *= al1;
        }

        // ---- P fragments (hi/lo) ----
        uint32_t pah[2][4], pal[2][4];
#pragma unroll
        for (int ksp = 0; ksp < 2; ksp++) {
#pragma unroll
            for (int half = 0; half < 2; half++) {
                int nb = ksp * 2 + half;
                float p00 = sacc[nb][0], p01 = sacc[nb][1];
                float p10 = sacc[nb][2], p11 = sacc[nb][3];
                float h00 = __bfloat162float(__float2bfloat16(p00));
                float h01 = __bfloat162float(__float2bfloat16(p01));
                float h10 = __bfloat162float(__float2bfloat16(p10));
                float h11 = __bfloat162float(__float2bfloat16(p11));
                pah[ksp][half * 2 + 0] = pack_bf16x2(h00, h01);
                pah[ksp][half * 2 + 1] = pack_bf16x2(h10, h11);
                pal[ksp][half * 2 + 0] = pack_bf16x2(p00 - h00, p01 - h01);
                pal[ksp][half * 2 + 1] = pack_bf16x2(p10 - h10, p11 - h11);
            }
        }

        // ---- ctx += P V (3-pass split) ----
#pragma unroll
        for (int ksv = 0; ksv < 2; ksv++) {
#pragma unroll
            for (int np = 0; np < 16; np += 2) {
                uint32_t vbh[8], vbl[8];
#pragma unroll
                for (int q2 = 0; q2 < 2; q2++) {
                    int vrow = (np + q2) * 16 + (lane & 15);
                    int vc = ksv * 2 + (lane >> 4);
                    uint32_t voff = vrow * 64 + ((vc ^ ((vrow >> 1) & 3)) << 4);
                    ldsm4(vbh + 4 * q2, sb + SMV_HI + voff);
                    ldsm4(vbl + 4 * q2, sb + SMV_LO + voff);
                }
#pragma unroll
                for (int q2 = 0; q2 < 2; q2++)
#pragma unroll
                    for (int ss = 0; ss < 2; ss++) {
                        int nv = (np + q2) * 2 + ss;
                        mma16816(ctx[nv], pah[ksv], vbh[q2 * 4 + ss], vbh[q2 * 4 + ss + 2]);
                    }
#pragma unroll
                for (int q2 = 0; q2 < 2; q2++)
#pragma unroll
                    for (int ss = 0; ss < 2; ss++) {
                        int nv = (np + q2) * 2 + ss;
                        mma16816(ctx[nv], pah[ksv], vbl[q2 * 4 + ss], vbl[q2 * 4 + ss + 2]);
                    }
#pragma unroll
                for (int q2 = 0; q2 < 2; q2++)
#pragma unroll
                    for (int ss = 0; ss < 2; ss++) {
                        int nv = (np + q2) * 2 + ss;
                        mma16816(ctx[nv], pal[ksv], vbh[q2 * 4 + ss], vbh[q2 * 4 + ss + 2]);
                    }
            }
        }
        __syncthreads();   // KV buffer reuse guard (single-buffered)
    }

    // ---- epilogue: normalize, split-store ctx ----
    float inv0 = 1.f / l0, inv1 = 1.f / l1;
    int tr0 = qb * BQ2 + w * 16 + (lane >> 2), tr1 = tr0 + 8;
#pragma unroll
    for (int nv = 0; nv < 32; nv++) {
        int col = h * 256 + nv * 8 + (lane & 3) * 2;
        size_t o0 = (size_t)tr0 * DM_ + col;
        size_t o1 = (size_t)tr1 * DM_ + col;
        split_store(ctx[nv][0] * inv0, chi + o0,     clo + o0);
        split_store(ctx[nv][1] * inv0, chi + o0 + 1, clo + o0 + 1);
        split_store(ctx[nv][2] * inv1, chi + o1,     clo + o1);
        split_store(ctx[nv][3] * inv1, chi + o1 + 1, clo + o1 + 1);
    }
}

// ---------------- launch ----------------
extern "C" void kernel_launch(void* const* d_in, const int* in_sizes, int n_in,
                              void* d_out, int out_size) {
    const int*   positions = (const int*)  d_in[0];
    const float* hidden    = (const float*)d_in[1];
    const float* ln_g      = (const float*)d_in[2];
    const float* ln_b      = (const float*)d_in[3];
    const float* w_qkv     = (const float*)d_in[4];
    const float* w_out     = (const float*)d_in[5];
    const float* w_fc_in   = (const float*)d_in[6];
    const float* b_fc_in   = (const float*)d_in[7];
    const float* w_fc_out  = (const float*)d_in[8];
    const float* b_fc_out  = (const float*)d_in[9];
    float* out = (float*)d_out;

    __nv_bfloat16 *wqh, *wql, *woh, *wol, *wih, *wil, *wfh, *wfl;
    __nv_bfloat16 *lnh, *lnl, *ach, *acl, *cxh, *cxl;
    __nv_bfloat16 *pqh, *pql, *pkh, *pkl, *pvh, *pvl;
    float *p_qkv, *p_att;
    cudaGetSymbolAddress((void**)&wqh, g_wqkvT_hi);  cudaGetSymbolAddress((void**)&wql, g_wqkvT_lo);
    cudaGetSymbolAddress((void**)&woh, g_woutT_hi);  cudaGetSymbolAddress((void**)&wol, g_woutT_lo);
    cudaGetSymbolAddress((void**)&wih, g_wfciT_hi);  cudaGetSymbolAddress((void**)&wil, g_wfciT_lo);
    cudaGetSymbolAddress((void**)&wfh, g_wfcoT_hi);  cudaGetSymbolAddress((void**)&wfl, g_wfcoT_lo);
    cudaGetSymbolAddress((void**)&lnh, g_ln_hi);     cudaGetSymbolAddress((void**)&lnl, g_ln_lo);
    cudaGetSymbolAddress((void**)&ach, g_act_hi);    cudaGetSymbolAddress((void**)&acl, g_act_lo);
    cudaGetSymbolAddress((void**)&cxh, g_ctx_hi);    cudaGetSymbolAddress((void**)&cxl, g_ctx_lo);
    cudaGetSymbolAddress((void**)&pqh, g_qh);        cudaGetSymbolAddress((void**)&pql, g_ql);
    cudaGetSymbolAddress((void**)&pkh, g_kh);        cudaGetSymbolAddress((void**)&pkl, g_kl);
    cudaGetSymbolAddress((void**)&pvh, g_vth);       cudaGetSymbolAddress((void**)&pvl, g_vtl);
    cudaGetSymbolAddress((void**)&p_qkv, g_qkv);
    cudaGetSymbolAddress((void**)&p_att, g_attnout);

    cudaFuncSetAttribute(mma_gemm<0>, cudaFuncAttributeMaxDynamicSharedMemorySize, GEMM_SMEM);
    cudaFuncSetAttribute(mma_gemm<1>, cudaFuncAttributeMaxDynamicSharedMemorySize, GEMM_SMEM);
    cudaFuncSetAttribute(mma_gemm<2>, cudaFuncAttributeMaxDynamicSharedMemorySize, GEMM_SMEM);
    cudaFuncSetAttribute(attn_mma,    cudaFuncAttributeMaxDynamicSharedMemorySize, ATT_SMEM);

    static cudaStream_t s1 = nullptr, s2 = nullptr;
    static cudaEvent_t evFork = nullptr, evLN = nullptr, evJoin1 = nullptr, evJoin2 = nullptr;
    if (!s1) {
        cudaStreamCreateWithFlags(&s1, cudaStreamNonBlocking);
        cudaStreamCreateWithFlags(&s2, cudaStreamNonBlocking);
        cudaEventCreateWithFlags(&evFork,  cudaEventDisableTiming);
        cudaEventCreateWithFlags(&evLN,    cudaEventDisableTiming);
        cudaEventCreateWithFlags(&evJoin1, cudaEventDisableTiming);
        cudaEventCreateWithFlags(&evJoin2, cudaEventDisableTiming);
    }

    dim3 cb(32, 8);

    cudaEventRecord(evFork, 0);
    cudaStreamWaitEvent(s1, evFork, 0);
    cudaStreamWaitEvent(s2, evFork, 0);

    // ---- chain A prep (s1): attention-path weights + LN ----
    convT_kernel<<<dim3(3 * DM_ / 32, DM_ / 32), cb, 0, s1>>>(w_qkv, wqh, wql, DM_, 3 * DM_);
    convT_kernel<<<dim3(DM_ / 32,     DM_ / 32), cb, 0, s1>>>(w_out, woh, wol, DM_, DM_);
    ln_kernel<<<T_, 256, 0, s1>>>(hidden, ln_g, ln_b, lnh, lnl);
    cudaEventRecord(evLN, s1);

    // ---- chain B (s2): MLP weights, then fc_in -> fc_out ----
    convT_kernel<<<dim3(DFF_ / 32, DM_ / 32), cb, 0, s2>>>(w_fc_in,  wih, wil, DM_,  DFF_);
    convT_kernel<<<dim3(DM_ / 32, DFF_ / 32), cb, 0, s2>>>(w_fc_out, wfh, wfl, DFF_, DM_);
    cudaStreamWaitEvent(s2, evLN, 0);
    mma_gemm<1><<<(T_ / 128) * (DFF_ / 128), 256, GEMM_SMEM, s2>>>(
        lnh, lnl, wih, wil, nullptr, ach, acl, b_fc_in, nullptr, T_, DFF_, DM_);
    mma_gemm<2><<<(T_ / 128) * (DM_ / 128), 256, GEMM_SMEM, s2>>>(
        ach, acl, wfh, wfl, out, nullptr, nullptr, b_fc_out, hidden, T_, DM_, DFF_);
    cudaEventRecord(evJoin2, s2);

    // ---- chain A (s1): QKV -> fused rope+split -> attention -> out-proj ----
    mma_gemm<0><<<(T_ / 128) * (3 * DM_ / 128), 256, GEMM_SMEM, s1>>>(
        lnh, lnl, wqh, wql, p_qkv, nullptr, nullptr, nullptr, nullptr, T_, 3 * DM_, DM_);
    qksplit_rope<<<(2 * T_ * DM_ / 4) / 256, 256, 0, s1>>>(p_qkv, positions, pqh, pql, pkh, pkl);
    vsplitT_kernel<<<dim3(T_ / 32, HD_ / 32, H_), cb, 0, s1>>>(p_qkv, pvh, pvl);
    attn_mma<<<dim3(T_ / BQ2, H_), 128, ATT_SMEM, s1>>>(pqh, pql, pkh, pkl, pvh, pvl, cxh, cxl);
    mma_gemm<0><<<(T_ / 128) * (DM_ / 128), 256, GEMM_SMEM, s1>>>(
        cxh, cxl, woh, wol, p_att, nullptr, nullptr, nullptr, nullptr, T_, DM_, DM_);
    cudaEventRecord(evJoin1, s1);

    // ---- join, final merge ----
    cudaStreamWaitEvent(0, evJoin1, 0);
    cudaStreamWaitEvent(0, evJoin2, 0);
    add_kernel<<<(T_ * DM_ / 4) / 256, 256>>>(out, p_att);
}

// round 17
// speedup vs baseline: 1.0066x; 1.0066x over previous
#include <cuda_runtime.h>
#include <cuda_bf16.h>
#include <math.h>
#include <math_constants.h>
#include <cstdint>

#define T_   2048
#define DM_  4096
#define H_   16
#define HD_  256
#define RD_  64
#define DFF_ 16384

// ---------------- scratch (device globals) ----------------
__device__ __nv_bfloat16 g_wqkvT_hi[(size_t)3*DM_*DM_];
__device__ __nv_bfloat16 g_wqkvT_lo[(size_t)3*DM_*DM_];
__device__ __nv_bfloat16 g_woutT_hi[(size_t)DM_*DM_];
__device__ __nv_bfloat16 g_woutT_lo[(size_t)DM_*DM_];
__device__ __nv_bfloat16 g_wfciT_hi[(size_t)DFF_*DM_];
__device__ __nv_bfloat16 g_wfciT_lo[(size_t)DFF_*DM_];
__device__ __nv_bfloat16 g_wfcoT_hi[(size_t)DM_*DFF_];
__device__ __nv_bfloat16 g_wfcoT_lo[(size_t)DM_*DFF_];
__device__ __nv_bfloat16 g_ln_hi[(size_t)T_*DM_];
__device__ __nv_bfloat16 g_ln_lo[(size_t)T_*DM_];
__device__ __nv_bfloat16 g_act_hi[(size_t)T_*DFF_];
__device__ __nv_bfloat16 g_act_lo[(size_t)T_*DFF_];
__device__ __nv_bfloat16 g_ctx_hi[(size_t)T_*DM_];
__device__ __nv_bfloat16 g_ctx_lo[(size_t)T_*DM_];
__device__ float g_qkv[(size_t)T_*3*DM_];
__device__ float g_attnout[(size_t)T_*DM_];
// attention operand buffers ([H][T][HD] for q,k; [H][HD][T] for v transposed)
__device__ __nv_bfloat16 g_qh[(size_t)T_*DM_];
__device__ __nv_bfloat16 g_ql[(size_t)T_*DM_];
__device__ __nv_bfloat16 g_kh[(size_t)T_*DM_];
__device__ __nv_bfloat16 g_kl[(size_t)T_*DM_];
__device__ __nv_bfloat16 g_vth[(size_t)T_*DM_];
__device__ __nv_bfloat16 g_vtl[(size_t)T_*DM_];

// ---------------- PTX helpers (baseline features only) --------
__device__ __forceinline__ uint32_t smem_u32(const void* p) {
    uint32_t a;
    asm("{ .reg .u64 t; cvta.to.shared.u64 t, %1; cvt.u32.u64 %0, t; }" : "=r"(a) : "l"(p));
    return a;
}
__device__ __forceinline__ void cp_async16(uint32_t d, const void* g) {
    asm volatile("cp.async.cg.shared.global [%0], [%1], 16;" :: "r"(d), "l"(g));
}
#define CP_COMMIT()  asm volatile("cp.async.commit_group;" ::: "memory")
#define CP_WAIT1()   asm volatile("cp.async.wait_group 1;" ::: "memory")
#define CP_WAIT0()   asm volatile("cp.async.wait_group 0;" ::: "memory")

__device__ __forceinline__ void ldsm4(uint32_t* r, uint32_t addr) {
    asm volatile("ldmatrix.sync.aligned.m8n8.x4.shared.b16 {%0,%1,%2,%3}, [%4];"
                 : "=r"(r[0]), "=r"(r[1]), "=r"(r[2]), "=r"(r[3]) : "r"(addr));
}
__device__ __forceinline__ void mma16816(float* c, const uint32_t* a,
                                         uint32_t b0, uint32_t b1) {
    asm volatile("mma.sync.aligned.m16n8k16.row.col.f32.bf16.bf16.f32 "
                 "{%0,%1,%2,%3}, {%4,%5,%6,%7}, {%8,%9}, {%0,%1,%2,%3};"
                 : "+f"(c[0]), "+f"(c[1]), "+f"(c[2]), "+f"(c[3])
                 : "r"(a[0]), "r"(a[1]), "r"(a[2]), "r"(a[3]), "r"(b0), "r"(b1));
}
__device__ __forceinline__ uint32_t pack_bf16x2(float lo, float hi) {
    uint32_t r;
    asm("cvt.rn.bf16x2.f32 %0, %1, %2;" : "=r"(r) : "f"(hi), "f"(lo));
    return r;
}
__device__ __forceinline__ void split_store(float v, __nv_bfloat16* ph, __nv_bfloat16* pl) {
    __nv_bfloat16 h = __float2bfloat16(v);
    *ph = h;
    *pl = __float2bfloat16(v - __bfloat162float(h));
}

// ---------------- weight transpose + bf16 split (coalesced bf16x2 stores) ---
__global__ void convT_kernel(const float* __restrict__ W,
                             __nv_bfloat16* __restrict__ hi,
                             __nv_bfloat16* __restrict__ lo,
                             int Krows, int Ncols) {
    __shared__ float tile[32][33];
    int n0 = blockIdx.x * 32, k0 = blockIdx.y * 32;
    int tx = threadIdx.x, ty = threadIdx.y;       // 32 x 8
#pragma unroll
    for (int i = 0; i < 4; i++)
        tile[ty + 8 * i][tx] = W[(size_t)(k0 + ty + 8 * i) * Ncols + n0 + tx];
    __syncthreads();
#pragma unroll
    for (int it = 0; it < 2; it++) {
        int r  = ty + 8 * (2 * it + (tx >> 4));   // n within tile
        int kp = (tx & 15) * 2;                   // k pair
        float v0 = tile[kp][r], v1 = tile[kp + 1][r];
        size_t o = (size_t)(n0 + r) * Krows + k0 + kp;
        __nv_bfloat16 h0 = __float2bfloat16(v0);
        __nv_bfloat16 h1 = __float2bfloat16(v1);
        __nv_bfloat162 hh; hh.x = h0; hh.y = h1;
        *(__nv_bfloat162*)(hi + o) = hh;
        __nv_bfloat162 ll;
        ll.x = __float2bfloat16(v0 - __bfloat162float(h0));
        ll.y = __float2bfloat16(v1 - __bfloat162float(h1));
        *(__nv_bfloat162*)(lo + o) = ll;
    }
}

// ---------------- LayerNorm -> bf16 hi/lo ----------------
__global__ void ln_kernel(const float* __restrict__ x,
                          const float* __restrict__ gamma,
                          const float* __restrict__ beta,
                          __nv_bfloat16* __restrict__ ohi,
                          __nv_bfloat16* __restrict__ olo) {
    int row = blockIdx.x;
    const float4* xr = (const float4*)(x + (size_t)row * DM_);
    float4 v[4];
    float sum = 0.f, sq = 0.f;
#pragma unroll
    for (int i = 0; i < 4; i++) {
        v[i] = xr[threadIdx.x + 256 * i];
        sum += v[i].x + v[i].y + v[i].z + v[i].w;
        sq  += v[i].x * v[i].x + v[i].y * v[i].y + v[i].z * v[i].z + v[i].w * v[i].w;
    }
#pragma unroll
    for (int o = 16; o; o >>= 1) {
        sum += __shfl_xor_sync(0xffffffffu, sum, o);
        sq  += __shfl_xor_sync(0xffffffffu, sq,  o);
    }
    __shared__ float ssum[8], ssq[8];
    int warp = threadIdx.x >> 5, lane = threadIdx.x & 31;
    if (lane == 0) { ssum[warp] = sum; ssq[warp] = sq; }
    __syncthreads();
    sum = 0.f; sq = 0.f;
#pragma unroll
    for (int i = 0; i < 8; i++) { sum += ssum[i]; sq += ssq[i]; }
    float mu  = sum * (1.0f / DM_);
    float var = sq * (1.0f / DM_) - mu * mu;
    float inv = rsqrtf(var + 1e-5f);
    const float4* g4 = (const float4*)gamma;
    const float4* b4 = (const float4*)beta;
#pragma unroll
    for (int i = 0; i < 4; i++) {
        int idx = threadIdx.x + 256 * i;
        float4 g = g4[idx], b = b4[idx];
        size_t base = (size_t)row * DM_ + idx * 4;
        split_store((v[i].x - mu) * inv * g.x + b.x, ohi + base + 0, olo + base + 0);
        split_store((v[i].y - mu) * inv * g.y + b.y, ohi + base + 1, olo + base + 1);
        split_store((v[i].z - mu) * inv * g.z + b.z, ohi + base + 2, olo + base + 2);
        split_store((v[i].w - mu) * inv * g.w + b.w, ohi + base + 3, olo + base + 3);
    }
}

// ---------------- fused RoPE + q/k split to [H][T][HD] bf16 hi/lo -----------
__global__ void qksplit_rope(const float* __restrict__ qkv,
                             const int* __restrict__ positions,
                             __nv_bfloat16* __restrict__ qh, __nv_bfloat16* __restrict__ ql,
                             __nv_bfloat16* __restrict__ kh, __nv_bfloat16* __restrict__ kl) {
    int idx = blockIdx.x * 256 + threadIdx.x;          // 0 .. 2*T*DM/4
    const int per = T_ * DM_ / 4;
    int half = idx >= per;
    int rem = idx - half * per;
    int t = rem / (DM_ / 4);
    int e4 = rem - t * (DM_ / 4);
    float4 v = *(const float4*)(qkv + (size_t)t * (3 * DM_) + half * DM_ + e4 * 4);
    int hh = (e4 * 4) >> 8;
    int hd = (e4 * 4) & 255;
    if (hd < RD_) {
        int i0 = hd >> 1;
        float p = (float)positions[t];
        float inv0 = (float)pow(10000.0, -(double)i0 / 32.0);
        float inv1 = (float)pow(10000.0, -(double)(i0 + 1) / 32.0);
        float s0, c0, s1, c1;
        sincosf(p * inv0, &s0, &c0);
        sincosf(p * inv1, &s1, &c1);
        float x1 = v.x, x2 = v.y;
        v.x = x1 * c0 - x2 * s0;
        v.y = x2 * c0 + x1 * s0;
        x1 = v.z; x2 = v.w;
        v.z = x1 * c1 - x2 * s1;
        v.w = x2 * c1 + x1 * s1;
    }
    size_t dst = ((size_t)(hh * T_ + t)) * 256 + hd;
    __nv_bfloat16 *oh = half ? kh : qh, *ol = half ? kl : ql;
    split_store(v.x, oh + dst + 0, ol + dst + 0);
    split_store(v.y, oh + dst + 1, ol + dst + 1);
    split_store(v.z, oh + dst + 2, ol + dst + 2);
    split_store(v.w, oh + dst + 3, ol + dst + 3);
}

// ---------------- v split + transpose to [H][HD][T] bf16 hi/lo --------
__global__ void vsplitT_kernel(const float* __restrict__ qkv,
                               __nv_bfloat16* __restrict__ vth, __nv_bfloat16* __restrict__ vtl) {
    __shared__ float tile[32][33];
    int t0 = blockIdx.x * 32, hd0 = blockIdx.y * 32, h = blockIdx.z;
    int tx = threadIdx.x, ty = threadIdx.y;
#pragma unroll
    for (int i = 0; i < 4; i++)
        tile[ty + 8 * i][tx] = qkv[(size_t)(t0 + ty + 8 * i) * (3 * DM_) + 2 * DM_ + h * 256 + hd0 + tx];
    __syncthreads();
#pragma unroll
    for (int i = 0; i < 4; i++) {
        int r = ty + 8 * i;                 // hd within tile
        float v = tile[tx][r];              // = V[t0+tx][hd0+r]
        size_t o = ((size_t)(h * 256 + hd0 + r)) * T_ + t0 + tx;
        split_store(v, vth + o, vtl + o);
    }
}

__device__ __forceinline__ float gelu_tanh(float x) {
    float x3 = x * x * x;
    float t  = tanhf(0.7978845608028654f * (x + 0.044715f * x3));
    return 0.5f * x * (1.0f + t);
}

// ---------------- final merge: out += attnout ----------------
__global__ void add_kernel(float* __restrict__ out, const float* __restrict__ a) {
    int i = blockIdx.x * blockDim.x + threadIdx.x;
    float4 o = ((const float4*)out)[i];
    float4 v = ((const float4*)a)[i];
    o.x += v.x; o.y += v.y; o.z += v.z; o.w += v.w;
    ((float4*)out)[i] = o;
}

// ---------------- mma.sync split-bf16 GEMM (unchanged from R10) -------
#define KC 32
#define ARR_BYTES 8192
#define AHI_OFF 0
#define ALO_OFF 8192
#define BHI_OFF 16384
#define BLO_OFF 24576
#define STAGE_BYTES 32768
#define NSTAGE 3
#define GEMM_SMEM (NSTAGE * STAGE_BYTES)

template <int EPI>
__global__ void __launch_bounds__(256, 2)
mma_gemm(const __nv_bfloat16* __restrict__ Ahi, const __nv_bfloat16* __restrict__ Alo,
         const __nv_bfloat16* __restrict__ Bhi, const __nv_bfloat16* __restrict__ Blo,
         float* __restrict__ C,
         __nv_bfloat16* __restrict__ Ohi, __nv_bfloat16* __restrict__ Olo,
         const float* __restrict__ bias, const float* __restrict__ res,
         int M, int N, int K) {
    extern __shared__ char smem[];
    const uint32_t sb0 = smem_u32(smem);
    int tid = threadIdx.x;
    int lane = tid & 31, wid = tid >> 5;
    int wm = wid >> 2, wn = wid & 3;

    int nbn = N / 128, nbm = M / 128;
    const int SWT = 8;
    int per = SWT * nbm;
    int ggrp = blockIdx.x / per, rem = blockIdx.x - ggrp * per;
    int bn0 = ggrp * SWT;
    int w = nbn - bn0; if (w > SWT) w = SWT;
    int bn = bn0 + rem % w;
    int bm = rem / w;

    float acc[4][4][4];
#pragma unroll
    for (int i = 0; i < 4; i++)
#pragma unroll
        for (int j = 0; j < 4; j++)
#pragma unroll
            for (int q = 0; q < 4; q++) acc[i][j][q] = 0.f;

    auto load_stage = [&](int s, int k0) {
        uint32_t sb = sb0 + s * STAGE_BYTES;
#pragma unroll
        for (int j = 0; j < 2; j++) {
            int id  = tid + 256 * j;
            int row = id >> 2, c = id & 3;
            uint32_t d = row * 64 + ((c ^ ((row >> 1) & 3)) << 4);
            size_t goA = (size_t)(bm * 128 + row) * K + k0 + c * 8;
            size_t goB = (size_t)(bn * 128 + row) * K + k0 + c * 8;
            cp_async16(sb + AHI_OFF + d, Ahi + goA);
            cp_async16(sb + ALO_OFF + d, Alo + goA);
            cp_async16(sb + BHI_OFF + d, Bhi + goB);
            cp_async16(sb + BLO_OFF + d, Blo + goB);
        }
    };

    load_stage(0, 0); CP_COMMIT();
    load_stage(1, KC); CP_COMMIT();

    int hi4 = lane >> 4;
    int rA[4], swA[4], rB0, rB1, swB0, swB1;
#pragma unroll
    for (int i = 0; i < 4; i++) {
        int r = wm * 64 + i * 16 + (lane & 15);
        rA[i] = r * 64;
        swA[i] = (r >> 1) & 3;
    }
    {
        int r0 = wn * 32 + (lane & 15);
        int r1 = r0 + 16;
        rB0 = r0 * 64; swB0 = (r0 >> 1) & 3;
        rB1 = r1 * 64; swB1 = (r1 >> 1) & 3;
    }

    int nk = K / KC;
    int st = 0, ld = 2;
    for (int kc = 0; kc < nk; kc++) {
        CP_WAIT1();
        __syncthreads();
        if (kc + 2 < nk) load_stage(ld, (kc + 2) * KC);
        CP_COMMIT();
        uint32_t base = sb0 + st * STAGE_BYTES;
#pragma unroll
        for (int ks = 0; ks < 2; ks++) {
            int c = ks * 2 + hi4;
            uint32_t bh[8], bl[8];
            ldsm4(bh,     base + BHI_OFF + rB0 + ((c ^ swB0) << 4));
            ldsm4(bh + 4, base + BHI_OFF + rB1 + ((c ^ swB1) << 4));
            ldsm4(bl,     base + BLO_OFF + rB0 + ((c ^ swB0) << 4));
            ldsm4(bl + 4, base + BLO_OFF + rB1 + ((c ^ swB1) << 4));
#pragma unroll
            for (int i = 0; i < 4; i++) {
                uint32_t ah[4], al[4];
                ldsm4(ah, base + AHI_OFF + rA[i] + ((c ^ swA[i]) << 4));
                ldsm4(al, base + ALO_OFF + rA[i] + ((c ^ swA[i]) << 4));
#pragma unroll
                for (int j = 0; j < 4; j++) {
                    int j2 = j >> 1, ss = j & 1;
                    uint32_t b0h = bh[j2 * 4 + ss], b1h = bh[j2 * 4 + ss + 2];
                    uint32_t b0l = bl[j2 * 4 + ss], b1l = bl[j2 * 4 + ss + 2];
                    mma16816(acc[i][j], ah, b0h, b1h);
                    mma16816(acc[i][j], ah, b0l, b1l);
                    mma16816(acc[i][j], al, b0h, b1h);
                }
            }
        }
        st = (st == 2) ? 0 : st + 1;
        ld = (ld == 2) ? 0 : ld + 1;
    }

    int gq = lane >> 2, cc = lane & 3;
#pragma unroll
    for (int i = 0; i < 4; i++) {
#pragma unroll
        for (int j = 0; j < 4; j++) {
            int row = bm * 128 + wm * 64 + i * 16 + gq;
            int col = bn * 128 + wn * 32 + j * 8 + 2 * cc;
            float* a4 = acc[i][j];
#pragma unroll
            for (int half = 0; half < 2; half++) {
                int r = row + 8 * half;
                float v0 = a4[2 * half], v1 = a4[2 * half + 1];
                size_t base = (size_t)r * N + col;
                if (EPI == 0) {
                    *(float2*)(C + base) = make_float2(v0, v1);
                } else if (EPI == 1) {
                    float g0 = gelu_tanh(v0 + bias[col]);
                    float g1 = gelu_tanh(v1 + bias[col + 1]);
                    split_store(g0, Ohi + base, Olo + base);
                    split_store(g1, Ohi + base + 1, Olo + base + 1);
                } else if (EPI == 2) {
                    float2 rr = *(const float2*)(res + base);
                    *(float2*)(C + base) = make_float2(v0 + bias[col] + rr.x,
                                                       v1 + bias[col + 1] + rr.y);
                } else {
                    float2 cur = *(float2*)(C + base);
                    *(float2*)(C + base) = make_float2(cur.x + v0, cur.y + v1);
                }
            }
        }
    }
}

// ---------------- tensor-core causal flash attention (R15 double-buffered) --
#define BQ2 64
#define BK2 32
#define SMQ_HI 0
#define SMQ_LO 32768
#define SMSTG0 65536
#define SMSTG  65536
#define SMK_HI 0
#define SMK_LO 16384
#define SMV_HI 32768
#define SMV_LO 49152
#define ATT_SMEM 196608

__global__ void __launch_bounds__(128, 1)
attn_mma(const __nv_bfloat16* __restrict__ qh, const __nv_bfloat16* __restrict__ ql,
         const __nv_bfloat16* __restrict__ kh, const __nv_bfloat16* __restrict__ kl,
         const __nv_bfloat16* __restrict__ vth, const __nv_bfloat16* __restrict__ vtl,
         __nv_bfloat16* __restrict__ chi, __nv_bfloat16* __restrict__ clo) {
    extern __shared__ char smem[];
    uint32_t sb = smem_u32(smem);
    int h = blockIdx.y;
    int qb = (gridDim.x - 1) - blockIdx.x;      // big tiles first
    int tid = threadIdx.x, lane = tid & 31, w = tid >> 5;

    auto load_q = [&]() {
#pragma unroll
        for (int j = 0; j < 16; j++) {
            int id = tid + 128 * j;             // 0..2047
            int row = id >> 5, c = id & 31;
            uint32_t d = row * 512 + ((c ^ ((row & 7) << 2)) << 4);
            size_t src = ((size_t)(h * T_ + qb * BQ2 + row)) * 256 + c * 8;
            cp_async16(sb + SMQ_HI + d, qh + src);
            cp_async16(sb + SMQ_LO + d, ql + src);
        }
    };
    auto load_kv = [&](int s, int kt) {
        uint32_t st = sb + SMSTG0 + s * SMSTG;
#pragma unroll
        for (int j = 0; j < 8; j++) {
            int id = tid + 128 * j;             // 0..1023
            int row = id >> 5, c = id & 31;
            uint32_t d = row * 512 + ((c ^ ((row & 7) << 2)) << 4);
            size_t src = ((size_t)(h * T_ + kt * BK2 + row)) * 256 + c * 8;
            cp_async16(st + SMK_HI + d, kh + src);
            cp_async16(st + SMK_LO + d, kl + src);
            int vrow = id >> 2, vc = id & 3;
            uint32_t vd = vrow * 64 + ((vc ^ ((vrow >> 1) & 3)) << 4);
            size_t vs = ((size_t)(h * 256 + vrow)) * T_ + kt * BK2 + vc * 8;
            cp_async16(st + SMV_HI + vd, vth + vs);
            cp_async16(st + SMV_LO + vd, vtl + vs);
        }
    };

    float ctx[32][4];
#pragma unroll
    for (int i = 0; i < 32; i++)
#pragma unroll
        for (int q = 0; q < 4; q++) ctx[i][q] = 0.f;
    float m0 = -CUDART_INF_F, m1 = -CUDART_INF_F, l0 = 0.f, l1 = 0.f;

    int ntiles = 2 * qb + 2;
    load_q(); load_kv(0, 0); CP_COMMIT();
    int s = 0;
    for (int kt = 0; kt < ntiles; kt++) {
        CP_WAIT0();
        __syncthreads();
        if (kt + 1 < ntiles) { load_kv(s ^ 1, kt + 1); CP_COMMIT(); }
        uint32_t stg = sb + SMSTG0 + s * SMSTG;

        // ---- S = Q K^T (3-pass split) ----
        float sacc[4][4];
#pragma unroll
        for (int nb = 0; nb < 4; nb++)
#pragma unroll
            for (int q = 0; q < 4; q++) sacc[nb][q] = 0.f;
#pragma unroll 4
        for (int ks = 0; ks < 16; ks++) {
            int arow = w * 16 + (lane & 15);
            int ac = ks * 2 + (lane >> 4);
            uint32_t aoff = arow * 512 + ((ac ^ ((arow & 7) << 2)) << 4);
            uint32_t qhf[4], qlf[4];
            ldsm4(qhf, sb + SMQ_HI + aoff);
            ldsm4(qlf, sb + SMQ_LO + aoff);
            uint32_t kbh[8], kbl[8];
#pragma unroll
            for (int p2 = 0; p2 < 2; p2++) {
                int krow = p2 * 16 + (lane & 15);
                uint32_t koff = krow * 512 + ((ac ^ ((krow & 7) << 2)) << 4);
                ldsm4(kbh + 4 * p2, stg + SMK_HI + koff);
                ldsm4(kbl + 4 * p2, stg + SMK_LO + koff);
            }
#pragma unroll
            for (int nb = 0; nb < 4; nb++) {
                int p2 = nb >> 1, ss = nb & 1;
                mma16816(sacc[nb], qhf, kbh[p2 * 4 + ss], kbh[p2 * 4 + ss + 2]);
            }
#pragma unroll
            for (int nb = 0; nb < 4; nb++) {
                int p2 = nb >> 1, ss = nb & 1;
                mma16816(sacc[nb], qhf, kbl[p2 * 4 + ss], kbl[p2 * 4 + ss + 2]);
            }
#pragma unroll
            for (int nb = 0; nb < 4; nb++) {
                int p2 = nb >> 1, ss = nb & 1;
                mma16816(sacc[nb], qlf, kbh[p2 * 4 + ss], kbh[p2 * 4 + ss + 2]);
            }
        }

        // ---- mask + online softmax ----
        int r0 = qb * BQ2 + w * 16 + (lane >> 2);
        int r1 = r0 + 8;
        float mloc0 = -CUDART_INF_F, mloc1 = -CUDART_INF_F;
#pragma unroll
        for (int nb = 0; nb < 4; nb++) {
            int colb = kt * BK2 + nb * 8 + (lane & 3) * 2;
#pragma unroll
            for (int e = 0; e < 2; e++) {
                float v0 = sacc[nb][e] * 0.0625f;
                float v1 = sacc[nb][2 + e] * 0.0625f;
                if (colb + e > r0) v0 = -CUDART_INF_F;
                if (colb + e > r1) v1 = -CUDART_INF_F;
                sacc[nb][e] = v0; sacc[nb][2 + e] = v1;
                mloc0 = fmaxf(mloc0, v0); mloc1 = fmaxf(mloc1, v1);
            }
        }
        mloc0 = fmaxf(mloc0, __shfl_xor_sync(0xffffffffu, mloc0, 1));
        mloc0 = fmaxf(mloc0, __shfl_xor_sync(0xffffffffu, mloc0, 2));
        mloc1 = fmaxf(mloc1, __shfl_xor_sync(0xffffffffu, mloc1, 1));
        mloc1 = fmaxf(mloc1, __shfl_xor_sync(0xffffffffu, mloc1, 2));
        float mn0 = fmaxf(m0, mloc0), mn1 = fmaxf(m1, mloc1);
        float al0 = __expf(m0 - mn0), al1 = __expf(m1 - mn1);
        float ls0 = 0.f, ls1 = 0.f;
#pragma unroll
        for (int nb = 0; nb < 4; nb++) {
#pragma unroll
            for (int e = 0; e < 2; e++) {
                float p0 = __expf(sacc[nb][e] - mn0);
                float p1 = __expf(sacc[nb][2 + e] - mn1);
                ls0 += p0; ls1 += p1;
                sacc[nb][e] = p0; sacc[nb][2 + e] = p1;
            }
        }
        ls0 += __shfl_xor_sync(0xffffffffu, ls0, 1);
        ls0 += __shfl_xor_sync(0xffffffffu, ls0, 2);
        ls1 += __shfl_xor_sync(0xffffffffu, ls1, 1);
        ls1 += __shfl_xor_sync(0xffffffffu, ls1, 2);
        l0 = l0 * al0 + ls0;
        l1 = l1 * al1 + ls1;
        m0 = mn0; m1 = mn1;
#pragma unroll
        for (int nv = 0; nv < 32; nv++) {
            ctx[nv][0] *= al0; ctx[nv][1] *= al0;
            ctx[nv][2] *= al1; ctx[nv][3] *= al1;
        }

        // ---- P fragments (hi/lo) ----
        uint32_t pah[2][4], pal[2][4];
#pragma unroll
        for (int ksp = 0; ksp < 2; ksp++) {
#pragma unroll
            for (int half = 0; half < 2; half++) {
                int nb = ksp * 2 + half;
                float p00 = sacc[nb][0], p01 = sacc[nb][1];
                float p10 = sacc[nb][2], p11 = sacc[nb][3];
                float h00 = __bfloat162float(__float2bfloat16(p00));
                float h01 = __bfloat162float(__float2bfloat16(p01));
                float h10 = __bfloat162float(__float2bfloat16(p10));
                float h11 = __bfloat162float(__float2bfloat16(p11));
                pah[ksp][half * 2 + 0] = pack_bf16x2(h00, h01);
                pah[ksp][half * 2 + 1] = pack_bf16x2(h10, h11);
                pal[ksp][half * 2 + 0] = pack_bf16x2(p00 - h00, p01 - h01);
                pal[ksp][half * 2 + 1] = pack_bf16x2(p10 - h10, p11 - h11);
            }
        }

        // ---- ctx += P V (3-pass split) ----
#pragma unroll
        for (int ksv = 0; ksv < 2; ksv++) {
#pragma unroll
            for (int np = 0; np < 16; np += 2) {
                uint32_t vbh[8], vbl[8];
#pragma unroll
                for (int q2 = 0; q2 < 2; q2++) {
                    int vrow = (np + q2) * 16 + (lane & 15);
                    int vc = ksv * 2 + (lane >> 4);
                    uint32_t voff = vrow * 64 + ((vc ^ ((vrow >> 1) & 3)) << 4);
                    ldsm4(vbh + 4 * q2, stg + SMV_HI + voff);
                    ldsm4(vbl + 4 * q2, stg + SMV_LO + voff);
                }
#pragma unroll
                for (int q2 = 0; q2 < 2; q2++)
#pragma unroll
                    for (int ss = 0; ss < 2; ss++) {
                        int nv = (np + q2) * 2 + ss;
                        mma16816(ctx[nv], pah[ksv], vbh[q2 * 4 + ss], vbh[q2 * 4 + ss + 2]);
                    }
#pragma unroll
                for (int q2 = 0; q2 < 2; q2++)
#pragma unroll
                    for (int ss = 0; ss < 2; ss++) {
                        int nv = (np + q2) * 2 + ss;
                        mma16816(ctx[nv], pah[ksv], vbl[q2 * 4 + ss], vbl[q2 * 4 + ss + 2]);
                    }
#pragma unroll
                for (int q2 = 0; q2 < 2; q2++)
#pragma unroll
                    for (int ss = 0; ss < 2; ss++) {
                        int nv = (np + q2) * 2 + ss;
                        mma16816(ctx[nv], pal[ksv], vbh[q2 * 4 + ss], vbh[q2 * 4 + ss + 2]);
                    }
            }
        }
        s ^= 1;
    }

    // ---- epilogue: normalize, split-store ctx ----
    float inv0 = 1.f / l0, inv1 = 1.f / l1;
    int tr0 = qb * BQ2 + w * 16 + (lane >> 2), tr1 = tr0 + 8;
#pragma unroll
    for (int nv = 0; nv < 32; nv++) {
        int col = h * 256 + nv * 8 + (lane & 3) * 2;
        size_t o0 = (size_t)tr0 * DM_ + col;
        size_t o1 = (size_t)tr1 * DM_ + col;
        split_store(ctx[nv][0] * inv0, chi + o0,     clo + o0);
        split_store(ctx[nv][1] * inv0, chi + o0 + 1, clo + o0 + 1);
        split_store(ctx[nv][2] * inv1, chi + o1,     clo + o1);
        split_store(ctx[nv][3] * inv1, chi + o1 + 1, clo + o1 + 1);
    }
}

// ---------------- launch ----------------
extern "C" void kernel_launch(void* const* d_in, const int* in_sizes, int n_in,
                              void* d_out, int out_size) {
    const int*   positions = (const int*)  d_in[0];
    const float* hidden    = (const float*)d_in[1];
    const float* ln_g      = (const float*)d_in[2];
    const float* ln_b      = (const float*)d_in[3];
    const float* w_qkv     = (const float*)d_in[4];
    const float* w_out     = (const float*)d_in[5];
    const float* w_fc_in   = (const float*)d_in[6];
    const float* b_fc_in   = (const float*)d_in[7];
    const float* w_fc_out  = (const float*)d_in[8];
    const float* b_fc_out  = (const float*)d_in[9];
    float* out = (float*)d_out;

    __nv_bfloat16 *wqh, *wql, *woh, *wol, *wih, *wil, *wfh, *wfl;
    __nv_bfloat16 *lnh, *lnl, *ach, *acl, *cxh, *cxl;
    __nv_bfloat16 *pqh, *pql, *pkh, *pkl, *pvh, *pvl;
    float *p_qkv, *p_att;
    cudaGetSymbolAddress((void**)&wqh, g_wqkvT_hi);  cudaGetSymbolAddress((void**)&wql, g_wqkvT_lo);
    cudaGetSymbolAddress((void**)&woh, g_woutT_hi);  cudaGetSymbolAddress((void**)&wol, g_woutT_lo);
    cudaGetSymbolAddress((void**)&wih, g_wfciT_hi);  cudaGetSymbolAddress((void**)&wil, g_wfciT_lo);
    cudaGetSymbolAddress((void**)&wfh, g_wfcoT_hi);  cudaGetSymbolAddress((void**)&wfl, g_wfcoT_lo);
    cudaGetSymbolAddress((void**)&lnh, g_ln_hi);     cudaGetSymbolAddress((void**)&lnl, g_ln_lo);
    cudaGetSymbolAddress((void**)&ach, g_act_hi);    cudaGetSymbolAddress((void**)&acl, g_act_lo);
    cudaGetSymbolAddress((void**)&cxh, g_ctx_hi);    cudaGetSymbolAddress((void**)&cxl, g_ctx_lo);
    cudaGetSymbolAddress((void**)&pqh, g_qh);        cudaGetSymbolAddress((void**)&pql, g_ql);
    cudaGetSymbolAddress((void**)&pkh, g_kh);        cudaGetSymbolAddress((void**)&pkl, g_kl);
    cudaGetSymbolAddress((void**)&pvh, g_vth);       cudaGetSymbolAddress((void**)&pvl, g_vtl);
    cudaGetSymbolAddress((void**)&p_qkv, g_qkv);
    cudaGetSymbolAddress((void**)&p_att, g_attnout);

    cudaFuncSetAttribute(mma_gemm<0>, cudaFuncAttributeMaxDynamicSharedMemorySize, GEMM_SMEM);
    cudaFuncSetAttribute(mma_gemm<1>, cudaFuncAttributeMaxDynamicSharedMemorySize, GEMM_SMEM);
    cudaFuncSetAttribute(mma_gemm<2>, cudaFuncAttributeMaxDynamicSharedMemorySize, GEMM_SMEM);
    cudaFuncSetAttribute(attn_mma,    cudaFuncAttributeMaxDynamicSharedMemorySize, ATT_SMEM);

    static cudaStream_t s1 = nullptr, s2 = nullptr;
    static cudaEvent_t evFork = nullptr, evLN = nullptr, evJoin1 = nullptr, evJoin2 = nullptr;
    if (!s1) {
        cudaStreamCreateWithFlags(&s1, cudaStreamNonBlocking);
        cudaStreamCreateWithFlags(&s2, cudaStreamNonBlocking);
        cudaEventCreateWithFlags(&evFork,  cudaEventDisableTiming);
        cudaEventCreateWithFlags(&evLN,    cudaEventDisableTiming);
        cudaEventCreateWithFlags(&evJoin1, cudaEventDisableTiming);
        cudaEventCreateWithFlags(&evJoin2, cudaEventDisableTiming);
    }

    dim3 cb(32, 8);

    cudaEventRecord(evFork, 0);
    cudaStreamWaitEvent(s1, evFork, 0);
    cudaStreamWaitEvent(s2, evFork, 0);

    // ---- chain A prep (s1): attention-path weights + LN ----
    convT_kernel<<<dim3(3 * DM_ / 32, DM_ / 32), cb, 0, s1>>>(w_qkv, wqh, wql, DM_, 3 * DM_);
    convT_kernel<<<dim3(DM_ / 32,     DM_ / 32), cb, 0, s1>>>(w_out, woh, wol, DM_, DM_);
    ln_kernel<<<T_, 256, 0, s1>>>(hidden, ln_g, ln_b, lnh, lnl);
    cudaEventRecord(evLN, s1);

    // ---- chain B (s2): MLP weights, then fc_in -> fc_out ----
    convT_kernel<<<dim3(DFF_ / 32, DM_ / 32), cb, 0, s2>>>(w_fc_in,  wih, wil, DM_,  DFF_);
    convT_kernel<<<dim3(DM_ / 32, DFF_ / 32), cb, 0, s2>>>(w_fc_out, wfh, wfl, DFF_, DM_);
    cudaStreamWaitEvent(s2, evLN, 0);
    mma_gemm<1><<<(T_ / 128) * (DFF_ / 128), 256, GEMM_SMEM, s2>>>(
        lnh, lnl, wih, wil, nullptr, ach, acl, b_fc_in, nullptr, T_, DFF_, DM_);
    mma_gemm<2><<<(T_ / 128) * (DM_ / 128), 256, GEMM_SMEM, s2>>>(
        ach, acl, wfh, wfl, out, nullptr, nullptr, b_fc_out, hidden, T_, DM_, DFF_);
    cudaEventRecord(evJoin2, s2);

    // ---- chain A (s1): QKV -> fused rope+split -> attention -> out-proj ----
    mma_gemm<0><<<(T_ / 128) * (3 * DM_ / 128), 256, GEMM_SMEM, s1>>>(
        lnh, lnl, wqh, wql, p_qkv, nullptr, nullptr, nullptr, nullptr, T_, 3 * DM_, DM_);
    qksplit_rope<<<(2 * T_ * DM_ / 4) / 256, 256, 0, s1>>>(p_qkv, positions, pqh, pql, pkh, pkl);
    vsplitT_kernel<<<dim3(T_ / 32, HD_ / 32, H_), cb, 0, s1>>>(p_qkv, pvh, pvl);
    attn_mma<<<dim3(T_ / BQ2, H_), 128, ATT_SMEM, s1>>>(pqh, pql, pkh, pkl, pvh, pvl, cxh, cxl);
    mma_gemm<0><<<(T_ / 128) * (DM_ / 128), 256, GEMM_SMEM, s1>>>(
        cxh, cxl, woh, wol, p_att, nullptr, nullptr, nullptr, nullptr, T_, DM_, DM_);
    cudaEventRecord(evJoin1, s1);

    // ---- join, final merge ----
    cudaStreamWaitEvent(0, evJoin1, 0);
    cudaStreamWaitEvent(0, evJoin2, 0);
    add_kernel<<<(T_ * DM_ / 4) / 256, 256>>>(out, p_att);
}